// round 14
// baseline (speedup 1.0000x reference)
#include <cuda_runtime.h>
#include <cuda_fp16.h>
#include <cstdint>

#define NN   65536
#define INC  512
#define HD   1024
#define DIM  256

// ---------------- scratch (device globals) -----------------------------------
__device__ __half g_xh[NN * INC];
__device__ __half g_wh[3][INC * HD];
__device__ __half g_q[NN * HD];
__device__ __half g_k[NN * HD];
__device__ float g_colsum_p[1024 * INC];
__device__ float g_colsum[INC];
__device__ float g_vsum[HD];
__device__ float g_ksum_p2[512 * HD];
__device__ float g_ksum[HD];
__device__ float g_C_part[9 * HD * INC];
__device__ __half g_C[HD * INC];
__device__ __half g_kvb[4 * DIM * DIM];
__device__ float g_invden[NN * 4];

// ---------------- helpers ----------------------------------------------------
__device__ __forceinline__ uint32_t smem_u32(const void* p) {
    return (uint32_t)__cvta_generic_to_shared(p);
}
__device__ __forceinline__ void ldsm4(uint32_t* r, uint32_t a) {
    asm volatile("ldmatrix.sync.aligned.m8n8.x4.shared.b16 {%0,%1,%2,%3}, [%4];"
        : "=r"(r[0]), "=r"(r[1]), "=r"(r[2]), "=r"(r[3]) : "r"(a));
}
__device__ __forceinline__ void ldsm4t(uint32_t* r, uint32_t a) {
    asm volatile("ldmatrix.sync.aligned.m8n8.x4.trans.shared.b16 {%0,%1,%2,%3}, [%4];"
        : "=r"(r[0]), "=r"(r[1]), "=r"(r[2]), "=r"(r[3]) : "r"(a));
}
__device__ __forceinline__ void mma16816f(float* d, const uint32_t* a, const uint32_t* b) {
    asm volatile("mma.sync.aligned.m16n8k16.row.col.f32.f16.f16.f32 "
        "{%0,%1,%2,%3}, {%4,%5,%6,%7}, {%8,%9}, {%0,%1,%2,%3};"
        : "+f"(d[0]), "+f"(d[1]), "+f"(d[2]), "+f"(d[3])
        : "r"(a[0]), "r"(a[1]), "r"(a[2]), "r"(a[3]), "r"(b[0]), "r"(b[1]));
}
__device__ __forceinline__ void cp16(void* s, const void* g) {
    asm volatile("cp.async.cg.shared.global [%0], [%1], 16;"
        :: "r"(smem_u32(s)), "l"(g));
}
__device__ __forceinline__ void cp_commit() { asm volatile("cp.async.commit_group;"); }
template<int W> __device__ __forceinline__ void cp_wait() {
    asm volatile("cp.async.wait_group %0;" :: "n"(W));
}

// ---------------- cvt_x + colsum partials (fused), 512 blocks ----------------
__global__ void cvt_x_kernel(const float* __restrict__ x) {
    int p = blockIdx.x;                 // 512 blocks, 128 rows each
    int tid = threadIdx.x;              // 256
    int seg = tid & 127, half = tid >> 7;
    size_t r0 = (size_t)p * 128;
    float c0 = 0.f, c1 = 0.f, c2 = 0.f, c3 = 0.f;
    for (int i = half; i < 128; i += 2) {
        float4 f = ((const float4*)x)[(r0 + i) * 128 + seg];
        c0 += f.x; c1 += f.y; c2 += f.z; c3 += f.w;
        __half2* d = (__half2*)g_xh + (r0 + i) * 256 + seg * 2;
        d[0] = __floats2half2_rn(f.x, f.y);
        d[1] = __floats2half2_rn(f.z, f.w);
    }
    float* dst = &g_colsum_p[(p * 2 + half) * INC + seg * 4];
    dst[0] = c0; dst[1] = c1; dst[2] = c2; dst[3] = c3;
}
__global__ void colsum_red_kernel() {
    int c = blockIdx.x * 256 + threadIdx.x;     // grid.x = 2
    float s = 0.f;
    for (int p = 0; p < 1024; p++) s += g_colsum_p[p * INC + c];
    g_colsum[c] = s;
}
__global__ void vsum_kernel(const float* __restrict__ Wv, const float* __restrict__ bv) {
    int warp = threadIdx.x >> 5, lane = threadIdx.x & 31;
    int m = blockIdx.x * 8 + warp;               // grid = 128
    float s = 0.f;
    for (int kk = lane; kk < INC; kk += 32) s += g_colsum[kk] * Wv[kk * HD + m];
    #pragma unroll
    for (int o = 16; o > 0; o >>= 1) s += __shfl_xor_sync(0xffffffffu, s, o);
    if (lane == 0) g_vsum[m] = s + 65536.f * bv[m];
}

__global__ void cvt_w_kernel(const float* __restrict__ Wq,
                             const float* __restrict__ Wk,
                             const float* __restrict__ Wv) {
    int which = blockIdx.y;
    const float* src = which == 0 ? Wq : which == 1 ? Wk : Wv;
    int i = blockIdx.x * 256 + threadIdx.x;      // grid.x = 512
    float4 f = ((const float4*)src)[i];
    __half2* d2 = (__half2*)g_wh[which];
    d2[2 * i]     = __floats2half2_rn(f.x, f.y);
    d2[2 * i + 1] = __floats2half2_rn(f.z, f.w);
}

// ---------------- fused q,k GEMM + bias + L2-normalize + ksum ----------------
#define APITCH 72
#define BPITCH 264
#define ASTG (128 * APITCH)
#define BSTG (64 * BPITCH)
#define GEMM_SMEM_BYTES ((3 * (ASTG + BSTG)) * 2)

__global__ __launch_bounds__(256) void qk_kernel(const float* __restrict__ bq,
                                                 const float* __restrict__ bk) {
    extern __shared__ __half sm[];
    char* smc = (char*)sm;
    __half* As = sm;
    __half* Bs = sm + 3 * ASTG;

    int which = blockIdx.x >> 2;
    int n0 = (blockIdx.x & 3) * 256;
    size_t r0 = (size_t)blockIdx.y * 128;
    const __half* __restrict__ B = g_wh[which];
    __half* __restrict__ C = which == 0 ? g_q : g_k;
    const float* __restrict__ bias = which == 0 ? bq : bk;

    int tid = threadIdx.x, lane = tid & 31, warp = tid >> 5;
    int wm = (warp & 1) * 64, wn = (warp >> 1) * 64;
    int quad = lane >> 3, r8 = lane & 7;
    int arow = tid >> 3, aseg = tid & 7;
    int brow = tid >> 5, bseg = tid & 31;

    float acc[4][8][4];
    #pragma unroll
    for (int a = 0; a < 4; a++)
        #pragma unroll
        for (int b = 0; b < 8; b++)
            #pragma unroll
            for (int c = 0; c < 4; c++) acc[a][b][c] = 0.f;

    auto load_stage = [&](int st, int k0) {
        #pragma unroll
        for (int rr = 0; rr < 4; rr++)
            cp16(&As[st * ASTG + (arow + rr * 32) * APITCH + aseg * 8],
                 &g_xh[(r0 + arow + rr * 32) * INC + k0 + aseg * 8]);
        #pragma unroll
        for (int rr = 0; rr < 8; rr++)
            cp16(&Bs[st * BSTG + (brow + rr * 8) * BPITCH + bseg * 8],
                 &B[(size_t)(k0 + brow + rr * 8) * HD + n0 + bseg * 8]);
        cp_commit();
    };

    load_stage(0, 0);
    load_stage(1, 64);
    #pragma unroll 1
    for (int it = 0; it < 8; it++) {
        int st = it % 3;
        if (it < 7) cp_wait<1>(); else cp_wait<0>();
        __syncthreads();
        if (it + 2 < 8) load_stage((it + 2) % 3, (it + 2) * 64);
        #pragma unroll
        for (int ks = 0; ks < 64; ks += 16) {
            uint32_t af[4][4], bf[4][4];
            #pragma unroll
            for (int mi = 0; mi < 4; mi++)
                ldsm4(af[mi], smem_u32(&As[st * ASTG +
                    (wm + mi * 16 + (quad & 1) * 8 + r8) * APITCH + ks + (quad >> 1) * 8]));
            #pragma unroll
            for (int nj = 0; nj < 4; nj++)
                ldsm4t(bf[nj], smem_u32(&Bs[st * BSTG +
                    (ks + (quad & 1) * 8 + r8) * BPITCH + wn + nj * 16 + (quad >> 1) * 8]));
            #pragma unroll
            for (int mi = 0; mi < 4; mi++)
                #pragma unroll
                for (int nj = 0; nj < 4; nj++) {
                    mma16816f(acc[mi][2 * nj],     af[mi], &bf[nj][0]);
                    mma16816f(acc[mi][2 * nj + 1], af[mi], &bf[nj][2]);
                }
        }
    }

    int group = lane >> 2, t4 = lane & 3;
    float ss0[4] = {0.f, 0.f, 0.f, 0.f}, ss1[4] = {0.f, 0.f, 0.f, 0.f};
    #pragma unroll
    for (int mi = 0; mi < 4; mi++)
        #pragma unroll
        for (int ni = 0; ni < 8; ni++) {
            int c = n0 + wn + ni * 8 + t4 * 2;
            float b0 = __ldg(&bias[c]), b1 = __ldg(&bias[c + 1]);
            acc[mi][ni][0] += b0; acc[mi][ni][1] += b1;
            acc[mi][ni][2] += b0; acc[mi][ni][3] += b1;
            ss0[mi] += acc[mi][ni][0] * acc[mi][ni][0] + acc[mi][ni][1] * acc[mi][ni][1];
            ss1[mi] += acc[mi][ni][2] * acc[mi][ni][2] + acc[mi][ni][3] * acc[mi][ni][3];
        }

    #pragma unroll
    for (int mi = 0; mi < 4; mi++) {
        ss0[mi] += __shfl_xor_sync(0xffffffffu, ss0[mi], 1);
        ss0[mi] += __shfl_xor_sync(0xffffffffu, ss0[mi], 2);
        ss1[mi] += __shfl_xor_sync(0xffffffffu, ss1[mi], 1);
        ss1[mi] += __shfl_xor_sync(0xffffffffu, ss1[mi], 2);
    }
    float* ssbuf = (float*)smc;
    int wng = warp >> 1;
    if (t4 == 0) {
        #pragma unroll
        for (int mi = 0; mi < 4; mi++) {
            ssbuf[wng * 128 + wm + mi * 16 + group]     = ss0[mi];
            ssbuf[wng * 128 + wm + mi * 16 + group + 8] = ss1[mi];
        }
    }
    __syncthreads();
    #pragma unroll
    for (int mi = 0; mi < 4; mi++) {
        int ra = wm + mi * 16 + group;
        float s0 = ssbuf[ra] + ssbuf[128 + ra] + ssbuf[256 + ra] + ssbuf[384 + ra];
        int rb = ra + 8;
        float s1 = ssbuf[rb] + ssbuf[128 + rb] + ssbuf[256 + rb] + ssbuf[384 + rb];
        float i0 = rsqrtf(s0), i1 = rsqrtf(s1);
        #pragma unroll
        for (int ni = 0; ni < 8; ni++) {
            acc[mi][ni][0] *= i0; acc[mi][ni][1] *= i0;
            acc[mi][ni][2] *= i1; acc[mi][ni][3] *= i1;
        }
    }

    #pragma unroll
    for (int mi = 0; mi < 4; mi++) {
        size_t rA = r0 + wm + mi * 16 + group;
        #pragma unroll
        for (int ni = 0; ni < 8; ni++) {
            int c = n0 + wn + ni * 8 + t4 * 2;
            *(__half2*)&C[rA * HD + c] =
                __floats2half2_rn(acc[mi][ni][0], acc[mi][ni][1]);
            *(__half2*)&C[(rA + 8) * HD + c] =
                __floats2half2_rn(acc[mi][ni][2], acc[mi][ni][3]);
        }
    }

    if (which == 1) {
        float cs[8][2];
        #pragma unroll
        for (int ni = 0; ni < 8; ni++) {
            cs[ni][0] = 0.f; cs[ni][1] = 0.f;
            #pragma unroll
            for (int mi = 0; mi < 4; mi++) {
                cs[ni][0] += acc[mi][ni][0] + acc[mi][ni][2];
                cs[ni][1] += acc[mi][ni][1] + acc[mi][ni][3];
            }
            #pragma unroll
            for (int o = 4; o < 32; o <<= 1) {
                cs[ni][0] += __shfl_xor_sync(0xffffffffu, cs[ni][0], o);
                cs[ni][1] += __shfl_xor_sync(0xffffffffu, cs[ni][1], o);
            }
        }
        __syncthreads();
        float* cbuf = (float*)smc;
        if (lane < 4) {
            #pragma unroll
            for (int ni = 0; ni < 8; ni++) {
                cbuf[warp * 64 + ni * 8 + lane * 2]     = cs[ni][0];
                cbuf[warp * 64 + ni * 8 + lane * 2 + 1] = cs[ni][1];
            }
        }
        __syncthreads();
        int g2 = tid >> 6, cc = tid & 63;
        float s = cbuf[(2 * g2) * 64 + cc] + cbuf[(2 * g2 + 1) * 64 + cc];
        g_ksum_p2[blockIdx.y * HD + n0 + g2 * 64 + cc] = s;
    }
}

// ---------------- ksum final reduce ------------------------------------------
__global__ void ksum_red_kernel() {
    int c = blockIdx.x * 256 + threadIdx.x;   // grid.x = 4
    float s = 0.f;
    for (int p = 0; p < 512; p++) s += g_ksum_p2[p * HD + c];
    g_ksum[c] = s;
}

// ---------------- invden[n,h] = 1/(qn . ksum[h] + N) -------------------------
__global__ void invden_kernel() {
    int wg = blockIdx.x * 8 + (threadIdx.x >> 5);
    int lane = threadIdx.x & 31, h = wg & 3;
    size_t base = (size_t)wg * 256 + lane * 8;
    uint4 raw = *(const uint4*)&g_q[base];
    __half2* p = (__half2*)&raw;
    const float* ks = &g_ksum[h * 256 + lane * 8];
    float s = 0.f;
    #pragma unroll
    for (int i = 0; i < 4; i++) {
        float2 f = __half22float2(p[i]);
        s += f.x * ks[2 * i] + f.y * ks[2 * i + 1];
    }
    #pragma unroll
    for (int o = 16; o > 0; o >>= 1) s += __shfl_xor_sync(0xffffffffu, s, o);
    if (lane == 0) g_invden[wg] = 1.f / (s + 65536.f);
}

// ---------------- C = kn^T @ x : [1024, 512], 9-way split-K ------------------
#define CA_PITCH 136
#define CB_PITCH 264
#define CA_STG (64 * CA_PITCH)
#define CB_STG (64 * CB_PITCH)
#define C_SMEM_BYTES ((3 * (CA_STG + CB_STG)) * 2)
#define NCHUNK 9
#define STRIPS_PER_CHUNK 114

__global__ __launch_bounds__(256) void c_kernel() {
    extern __shared__ __half sm[];
    __half* As = sm;
    __half* Bs = sm + 3 * CA_STG;

    int tid = threadIdx.x, lane = tid & 31, warp = tid >> 5;
    int wm = (warp & 1) * 64, wn = (warp >> 1) * 64;
    int m0 = blockIdx.x * 128;
    int j0 = blockIdx.y * 256;
    int chunk = blockIdx.z;
    int s0 = chunk * STRIPS_PER_CHUNK;
    int s1 = min(1024, s0 + STRIPS_PER_CHUNK);
    int L = s1 - s0;
    int quad = lane >> 3, r8 = lane & 7;
    int arow = tid >> 4, aseg = tid & 15;
    int brow = tid >> 5, bseg = tid & 31;

    float acc[4][8][4];
    #pragma unroll
    for (int a = 0; a < 4; a++)
        #pragma unroll
        for (int b = 0; b < 8; b++)
            #pragma unroll
            for (int c = 0; c < 4; c++) acc[a][b][c] = 0.f;

    auto load_stage = [&](int st, int strip) {
        size_t nb = (size_t)(s0 + strip) * 64;
        #pragma unroll
        for (int rr = 0; rr < 4; rr++)
            cp16(&As[st * CA_STG + (arow + rr * 16) * CA_PITCH + aseg * 8],
                 &g_k[(nb + arow + rr * 16) * HD + m0 + aseg * 8]);
        #pragma unroll
        for (int rr = 0; rr < 8; rr++)
            cp16(&Bs[st * CB_STG + (brow + rr * 8) * CB_PITCH + bseg * 8],
                 &g_xh[(nb + brow + rr * 8) * INC + j0 + bseg * 8]);
        cp_commit();
    };

    load_stage(0, 0);
    load_stage(1, 1);
    #pragma unroll 1
    for (int it = 0; it < L; it++) {
        int st = it % 3;
        if (it < L - 1) cp_wait<1>(); else cp_wait<0>();
        __syncthreads();
        if (it + 2 < L) load_stage((it + 2) % 3, it + 2);
        #pragma unroll
        for (int ks = 0; ks < 64; ks += 16) {
            uint32_t af[4][4], bf[4][4];
            #pragma unroll
            for (int mi = 0; mi < 4; mi++)
                ldsm4t(af[mi], smem_u32(&As[st * CA_STG +
                    (ks + (quad >> 1) * 8 + r8) * CA_PITCH + wm + mi * 16 + (quad & 1) * 8]));
            #pragma unroll
            for (int nj = 0; nj < 4; nj++)
                ldsm4t(bf[nj], smem_u32(&Bs[st * CB_STG +
                    (ks + (quad & 1) * 8 + r8) * CB_PITCH + wn + nj * 16 + (quad >> 1) * 8]));
            #pragma unroll
            for (int mi = 0; mi < 4; mi++)
                #pragma unroll
                for (int nj = 0; nj < 4; nj++) {
                    mma16816f(acc[mi][2 * nj],     af[mi], &bf[nj][0]);
                    mma16816f(acc[mi][2 * nj + 1], af[mi], &bf[nj][2]);
                }
        }
    }
    int group = lane >> 2, t4 = lane & 3;
    float* dst = &g_C_part[(size_t)chunk * (HD * INC)];
    #pragma unroll
    for (int mi = 0; mi < 4; mi++) {
        int rm = m0 + wm + mi * 16 + group;
        #pragma unroll
        for (int ni = 0; ni < 8; ni++) {
            int c = j0 + wn + ni * 8 + t4 * 2;
            *(float2*)&dst[rm * INC + c]       = make_float2(acc[mi][ni][0], acc[mi][ni][1]);
            *(float2*)&dst[(rm + 8) * INC + c] = make_float2(acc[mi][ni][2], acc[mi][ni][3]);
        }
    }
}

__global__ void cred_kernel() {
    int i = blockIdx.x * 256 + threadIdx.x;      // grid = 2048
    float s = 0.f;
    #pragma unroll
    for (int p = 0; p < NCHUNK; p++) s += g_C_part[(size_t)p * (HD * INC) + i];
    g_C[i] = __float2half(s);
}

// -------- kv_h = C_h @ Wv_h + ksum_h (x) bv_h : [4][256][256] -> f16 ---------
__global__ __launch_bounds__(256) void kvsmall_kernel(const float* __restrict__ bv) {
    __shared__ __half As[128][72];
    __shared__ __half Bs[64][136];
    int h = blockIdx.z;
    int m0 = blockIdx.x * 128;
    int d0 = blockIdx.y * 128;
    int tid = threadIdx.x, lane = tid & 31, warp = tid >> 5;
    int wm = (warp & 1) * 64, wn = (warp >> 1) * 32;
    int quad = lane >> 3, r8 = lane & 7;
    int arow = tid >> 3, aseg = tid & 7;
    int brow = tid >> 4, bseg = tid & 15;

    float acc[4][4][4];
    #pragma unroll
    for (int a = 0; a < 4; a++)
        #pragma unroll
        for (int b = 0; b < 4; b++)
            #pragma unroll
            for (int c = 0; c < 4; c++) acc[a][b][c] = 0.f;

    #pragma unroll 1
    for (int kt = 0; kt < 8; kt++) {
        int k0 = kt * 64;
        __syncthreads();
        #pragma unroll
        for (int rr = 0; rr < 4; rr++)
            *(uint4*)&As[arow + rr * 32][aseg * 8] =
                *(const uint4*)&g_C[(size_t)(h * 256 + m0 + arow + rr * 32) * INC + k0 + aseg * 8];
        #pragma unroll
        for (int rr = 0; rr < 4; rr++)
            *(uint4*)&Bs[brow + rr * 16][bseg * 8] =
                *(const uint4*)&g_wh[2][(size_t)(k0 + brow + rr * 16) * HD + h * 256 + d0 + bseg * 8];
        __syncthreads();
        #pragma unroll
        for (int ks = 0; ks < 64; ks += 16) {
            uint32_t af[4][4], bf[2][4];
            #pragma unroll
            for (int mi = 0; mi < 4; mi++)
                ldsm4(af[mi], smem_u32(&As[wm + mi * 16 + (quad & 1) * 8 + r8][ks + (quad >> 1) * 8]));
            #pragma unroll
            for (int nj = 0; nj < 2; nj++)
                ldsm4t(bf[nj], smem_u32(&Bs[ks + (quad & 1) * 8 + r8][wn + nj * 16 + (quad >> 1) * 8]));
            #pragma unroll
            for (int mi = 0; mi < 4; mi++)
                #pragma unroll
                for (int nj = 0; nj < 2; nj++) {
                    mma16816f(acc[mi][2 * nj],     af[mi], &bf[nj][0]);
                    mma16816f(acc[mi][2 * nj + 1], af[mi], &bf[nj][2]);
                }
        }
    }

    int group = lane >> 2, t4 = lane & 3;
    #pragma unroll
    for (int mi = 0; mi < 4; mi++) {
        int rm = m0 + wm + mi * 16 + group;
        float ksA = g_ksum[h * 256 + rm], ksB = g_ksum[h * 256 + rm + 8];
        #pragma unroll
        for (int ni = 0; ni < 4; ni++) {
            int c = d0 + wn + ni * 8 + t4 * 2;
            float b0 = __ldg(&bv[h * 256 + c]), b1 = __ldg(&bv[h * 256 + c + 1]);
            *(__half2*)&g_kvb[(size_t)(h * 256 + rm) * 256 + c] =
                __floats2half2_rn(acc[mi][ni][0] + ksA * b0, acc[mi][ni][1] + ksA * b1);
            *(__half2*)&g_kvb[(size_t)(h * 256 + rm + 8) * 256 + c] =
                __floats2half2_rn(acc[mi][ni][2] + ksB * b0, acc[mi][ni][3] + ksB * b1);
        }
    }
}

// ------ out: 64-row CTAs (256 thr), grid 1024, K=1024 ------------------------
#define OAPITCH 72
#define OASTG (64 * OAPITCH)
#define OBSTG (64 * BPITCH)
#define OUT_SMEM_BYTES ((3 * (OASTG + OBSTG)) * 2)

__global__ __launch_bounds__(256) void out_kernel(float* __restrict__ out) {
    extern __shared__ __half sm[];
    __half* As = sm;                  // [3][64][OAPITCH]
    __half* Bs = sm + 3 * OASTG;      // [3][64][BPITCH]

    size_t r0 = (size_t)blockIdx.x * 64;         // grid = 1024
    int tid = threadIdx.x, lane = tid & 31, warp = tid >> 5;
    int wm = (warp & 1) * 32, wn = (warp >> 1) * 64;
    int quad = lane >> 3, r8 = lane & 7;
    int arow = tid >> 2, aseg = tid & 3;
    int brow = tid >> 5, bseg = tid & 31;

    float acc[2][8][4];
    #pragma unroll
    for (int a = 0; a < 2; a++)
        #pragma unroll
        for (int b = 0; b < 8; b++)
            #pragma unroll
            for (int c = 0; c < 4; c++) acc[a][b][c] = 0.f;

    uint4 aR[2];
    float invR;

    auto ldgA = [&](int kit) {
        int k0 = kit * 64, h = k0 >> 8;
        size_t row = r0 + arow;
        aR[0] = *(const uint4*)&g_q[row * HD + k0 + aseg * 8];
        aR[1] = *(const uint4*)&g_q[row * HD + k0 + (aseg + 4) * 8];
        invR = g_invden[row * 4 + h];
    };
    auto stsA = [&](int kit) {
        int st = kit % 3;
        float iv = invR * 65536.f;
        #pragma unroll
        for (int rr = 0; rr < 2; rr++) {
            __half2* p = (__half2*)&aR[rr];
            uint4 o;
            __half2* q = (__half2*)&o;
            #pragma unroll
            for (int j = 0; j < 4; j++) {
                float2 f = __half22float2(p[j]);
                q[j] = __floats2half2_rn(f.x * iv, f.y * iv);
            }
            *(uint4*)&As[st * OASTG + arow * OAPITCH + (aseg + rr * 4) * 8] = o;
        }
    };
    auto cpB = [&](int kit) {
        int st = kit % 3, k0 = kit * 64;
        #pragma unroll
        for (int rr = 0; rr < 8; rr++)
            cp16(&Bs[st * OBSTG + (brow + rr * 8) * BPITCH + bseg * 8],
                 &g_kvb[(size_t)(k0 + brow + rr * 8) * 256 + bseg * 8]);
        cp_commit();
    };

    ldgA(0); stsA(0);
    ldgA(1);
    cpB(0); cpB(1);
    #pragma unroll 1
    for (int it = 0; it < 16; it++) {
        int st = it % 3;
        if (it < 15) cp_wait<1>(); else cp_wait<0>();
        __syncthreads();
        if (it + 1 < 16) stsA(it + 1);
        if (it + 2 < 16) { ldgA(it + 2); cpB(it + 2); }
        #pragma unroll
        for (int ks = 0; ks < 64; ks += 16) {
            uint32_t af[2][4], bf[4][4];
            #pragma unroll
            for (int mi = 0; mi < 2; mi++)
                ldsm4(af[mi], smem_u32(&As[st * OASTG +
                    (wm + mi * 16 + (quad & 1) * 8 + r8) * OAPITCH + ks + (quad >> 1) * 8]));
            #pragma unroll
            for (int nj = 0; nj < 4; nj++)
                ldsm4t(bf[nj], smem_u32(&Bs[st * OBSTG +
                    (ks + (quad & 1) * 8 + r8) * BPITCH + wn + nj * 16 + (quad >> 1) * 8]));
            #pragma unroll
            for (int mi = 0; mi < 2; mi++)
                #pragma unroll
                for (int nj = 0; nj < 4; nj++) {
                    mma16816f(acc[mi][2 * nj],     af[mi], &bf[nj][0]);
                    mma16816f(acc[mi][2 * nj + 1], af[mi], &bf[nj][2]);
                }
        }
    }

    const float inv64k = 1.f / 65536.f;
    int group = lane >> 2, t4 = lane & 3;
    #pragma unroll
    for (int mi = 0; mi < 2; mi++) {
        size_t rA = r0 + wm + mi * 16 + group;
        size_t rB = rA + 8;
        float ia[4], ib[4];
        #pragma unroll
        for (int h = 0; h < 4; h++) {
            ia[h] = g_invden[rA * 4 + h];
            ib[h] = g_invden[rB * 4 + h];
        }
        #pragma unroll
        for (int ni = 0; ni < 8; ni++) {
            int c = wn + ni * 8 + t4 * 2;
            float roa0 = 0.f, roa1 = 0.f, rob0 = 0.f, rob1 = 0.f;
            #pragma unroll
            for (int h = 0; h < 4; h++) {
                float v0 = __ldg(&g_vsum[h * 256 + c]);
                float v1 = __ldg(&g_vsum[h * 256 + c + 1]);
                roa0 += ia[h] * v0; roa1 += ia[h] * v1;
                rob0 += ib[h] * v0; rob1 += ib[h] * v1;
            }
            *(float2*)&out[rA * 256 + c] =
                make_float2(0.25f * (acc[mi][ni][0] * inv64k + roa0),
                            0.25f * (acc[mi][ni][1] * inv64k + roa1));
            *(float2*)&out[rB * 256 + c] =
                make_float2(0.25f * (acc[mi][ni][2] * inv64k + rob0),
                            0.25f * (acc[mi][ni][3] * inv64k + rob1));
        }
    }
}

// ---------------- launch (fork/join streams, capture-safe) -------------------
extern "C" void kernel_launch(void* const* d_in, const int* in_sizes, int n_in,
                              void* d_out, int out_size) {
    const float* x  = (const float*)d_in[0];
    const float* Wq = (const float*)d_in[1];
    const float* bq = (const float*)d_in[2];
    const float* Wk = (const float*)d_in[3];
    const float* bk = (const float*)d_in[4];
    const float* Wv = (const float*)d_in[5];
    const float* bv = (const float*)d_in[6];
    float* out = (float*)d_out;

    cudaFuncSetAttribute(qk_kernel,  cudaFuncAttributeMaxDynamicSharedMemorySize, GEMM_SMEM_BYTES);
    cudaFuncSetAttribute(c_kernel,   cudaFuncAttributeMaxDynamicSharedMemorySize, C_SMEM_BYTES);
    cudaFuncSetAttribute(out_kernel, cudaFuncAttributeMaxDynamicSharedMemorySize, OUT_SMEM_BYTES);

    cudaStream_t s1;
    cudaStreamCreateWithFlags(&s1, cudaStreamNonBlocking);
    cudaEvent_t evRoot, evX, evW, evQK, evSide;
    cudaEventCreateWithFlags(&evRoot, cudaEventDisableTiming);
    cudaEventCreateWithFlags(&evX, cudaEventDisableTiming);
    cudaEventCreateWithFlags(&evW, cudaEventDisableTiming);
    cudaEventCreateWithFlags(&evQK, cudaEventDisableTiming);
    cudaEventCreateWithFlags(&evSide, cudaEventDisableTiming);

    // fork: side stream must branch FROM the capture stream
    cudaEventRecord(evRoot, 0);
    cudaStreamWaitEvent(s1, evRoot, 0);

    // side stream: weight conversion concurrent with cvt_x
    cvt_w_kernel<<<dim3(512, 3), 256, 0, s1>>>(Wq, Wk, Wv);
    cudaEventRecord(evW, s1);

    // main stream: roofline chain
    cvt_x_kernel<<<512, 256>>>(x);
    cudaEventRecord(evX, 0);
    cudaStreamWaitEvent(0, evW, 0);
    qk_kernel<<<dim3(8, 512), 256, GEMM_SMEM_BYTES>>>(bq, bk);
    cudaEventRecord(evQK, 0);

    // side stream: colsum/vsum after cvt_x; ksum/invden after qk
    cudaStreamWaitEvent(s1, evX, 0);
    colsum_red_kernel<<<2, 256, 0, s1>>>();
    vsum_kernel<<<128, 256, 0, s1>>>(Wv, bv);
    cudaStreamWaitEvent(s1, evQK, 0);
    ksum_red_kernel<<<4, 256, 0, s1>>>();
    invden_kernel<<<32768, 256, 0, s1>>>();
    cudaEventRecord(evSide, s1);

    // main: C (overlaps side work), join, kvsmall, out
    c_kernel<<<dim3(8, 2, NCHUNK), 256, C_SMEM_BYTES>>>();
    cred_kernel<<<2048, 256>>>();
    cudaStreamWaitEvent(0, evSide, 0);
    kvsmall_kernel<<<dim3(2, 2, 4), 256>>>(bv);
    out_kernel<<<1024, 256, OUT_SMEM_BYTES>>>(out);
}

// round 15
// speedup vs baseline: 1.0259x; 1.0259x over previous
#include <cuda_runtime.h>
#include <cuda_fp16.h>
#include <cstdint>

#define NN   65536
#define INC  512
#define HD   1024
#define DIM  256

// ---------------- scratch (device globals) -----------------------------------
__device__ __half g_xh[NN * INC];
__device__ __half g_wh[3][INC * HD];
__device__ __half g_q[NN * HD];
__device__ __half g_k[NN * HD];
__device__ float g_colsum_p[1024 * INC];
__device__ float g_colsum[INC];
__device__ float g_vsum[HD];
__device__ float g_ksum_p2[512 * HD];
__device__ float g_ksum[HD];
__device__ float g_C_part[9 * HD * INC];
__device__ __half g_C[HD * INC];
__device__ __half g_kvb[4 * DIM * DIM];
__device__ float g_invden[NN * 4];

// ---------------- helpers ----------------------------------------------------
__device__ __forceinline__ uint32_t smem_u32(const void* p) {
    return (uint32_t)__cvta_generic_to_shared(p);
}
__device__ __forceinline__ void ldsm4(uint32_t* r, uint32_t a) {
    asm volatile("ldmatrix.sync.aligned.m8n8.x4.shared.b16 {%0,%1,%2,%3}, [%4];"
        : "=r"(r[0]), "=r"(r[1]), "=r"(r[2]), "=r"(r[3]) : "r"(a));
}
__device__ __forceinline__ void ldsm4t(uint32_t* r, uint32_t a) {
    asm volatile("ldmatrix.sync.aligned.m8n8.x4.trans.shared.b16 {%0,%1,%2,%3}, [%4];"
        : "=r"(r[0]), "=r"(r[1]), "=r"(r[2]), "=r"(r[3]) : "r"(a));
}
__device__ __forceinline__ void mma16816f(float* d, const uint32_t* a, const uint32_t* b) {
    asm volatile("mma.sync.aligned.m16n8k16.row.col.f32.f16.f16.f32 "
        "{%0,%1,%2,%3}, {%4,%5,%6,%7}, {%8,%9}, {%0,%1,%2,%3};"
        : "+f"(d[0]), "+f"(d[1]), "+f"(d[2]), "+f"(d[3])
        : "r"(a[0]), "r"(a[1]), "r"(a[2]), "r"(a[3]), "r"(b[0]), "r"(b[1]));
}
__device__ __forceinline__ void cp16(void* s, const void* g) {
    asm volatile("cp.async.cg.shared.global [%0], [%1], 16;"
        :: "r"(smem_u32(s)), "l"(g));
}
__device__ __forceinline__ void cp_commit() { asm volatile("cp.async.commit_group;"); }
template<int W> __device__ __forceinline__ void cp_wait() {
    asm volatile("cp.async.wait_group %0;" :: "n"(W));
}

// ---------------- cvt_x + colsum partials (fused), 512 blocks ----------------
__global__ void cvt_x_kernel(const float* __restrict__ x) {
    int p = blockIdx.x;                 // 512 blocks, 128 rows each
    int tid = threadIdx.x;              // 256
    int seg = tid & 127, half = tid >> 7;
    size_t r0 = (size_t)p * 128;
    float c0 = 0.f, c1 = 0.f, c2 = 0.f, c3 = 0.f;
    for (int i = half; i < 128; i += 2) {
        float4 f = ((const float4*)x)[(r0 + i) * 128 + seg];
        c0 += f.x; c1 += f.y; c2 += f.z; c3 += f.w;
        __half2* d = (__half2*)g_xh + (r0 + i) * 256 + seg * 2;
        d[0] = __floats2half2_rn(f.x, f.y);
        d[1] = __floats2half2_rn(f.z, f.w);
    }
    float* dst = &g_colsum_p[(p * 2 + half) * INC + seg * 4];
    dst[0] = c0; dst[1] = c1; dst[2] = c2; dst[3] = c3;
}
__global__ void colsum_red_kernel() {
    int c = blockIdx.x * 256 + threadIdx.x;     // grid.x = 2
    float s = 0.f;
    for (int p = 0; p < 1024; p++) s += g_colsum_p[p * INC + c];
    g_colsum[c] = s;
}
__global__ void vsum_kernel(const float* __restrict__ Wv, const float* __restrict__ bv) {
    int warp = threadIdx.x >> 5, lane = threadIdx.x & 31;
    int m = blockIdx.x * 8 + warp;               // grid = 128
    float s = 0.f;
    for (int kk = lane; kk < INC; kk += 32) s += g_colsum[kk] * Wv[kk * HD + m];
    #pragma unroll
    for (int o = 16; o > 0; o >>= 1) s += __shfl_xor_sync(0xffffffffu, s, o);
    if (lane == 0) g_vsum[m] = s + 65536.f * bv[m];
}

__global__ void cvt_w_kernel(const float* __restrict__ Wq,
                             const float* __restrict__ Wk,
                             const float* __restrict__ Wv) {
    int which = blockIdx.y;
    const float* src = which == 0 ? Wq : which == 1 ? Wk : Wv;
    int i = blockIdx.x * 256 + threadIdx.x;      // grid.x = 512
    float4 f = ((const float4*)src)[i];
    __half2* d2 = (__half2*)g_wh[which];
    d2[2 * i]     = __floats2half2_rn(f.x, f.y);
    d2[2 * i + 1] = __floats2half2_rn(f.z, f.w);
}

// ---------------- fused q,k GEMM + bias + L2-normalize + ksum ----------------
#define APITCH 72
#define BPITCH 264
#define ASTG (128 * APITCH)
#define BSTG (64 * BPITCH)
#define GEMM_SMEM_BYTES ((3 * (ASTG + BSTG)) * 2)

__global__ __launch_bounds__(256) void qk_kernel(const float* __restrict__ bq,
                                                 const float* __restrict__ bk) {
    extern __shared__ __half sm[];
    char* smc = (char*)sm;
    __half* As = sm;
    __half* Bs = sm + 3 * ASTG;

    int which = blockIdx.x >> 2;
    int n0 = (blockIdx.x & 3) * 256;
    size_t r0 = (size_t)blockIdx.y * 128;
    const __half* __restrict__ B = g_wh[which];
    __half* __restrict__ C = which == 0 ? g_q : g_k;
    const float* __restrict__ bias = which == 0 ? bq : bk;

    int tid = threadIdx.x, lane = tid & 31, warp = tid >> 5;
    int wm = (warp & 1) * 64, wn = (warp >> 1) * 64;
    int quad = lane >> 3, r8 = lane & 7;
    int arow = tid >> 3, aseg = tid & 7;
    int brow = tid >> 5, bseg = tid & 31;

    float acc[4][8][4];
    #pragma unroll
    for (int a = 0; a < 4; a++)
        #pragma unroll
        for (int b = 0; b < 8; b++)
            #pragma unroll
            for (int c = 0; c < 4; c++) acc[a][b][c] = 0.f;

    auto load_stage = [&](int st, int k0) {
        #pragma unroll
        for (int rr = 0; rr < 4; rr++)
            cp16(&As[st * ASTG + (arow + rr * 32) * APITCH + aseg * 8],
                 &g_xh[(r0 + arow + rr * 32) * INC + k0 + aseg * 8]);
        #pragma unroll
        for (int rr = 0; rr < 8; rr++)
            cp16(&Bs[st * BSTG + (brow + rr * 8) * BPITCH + bseg * 8],
                 &B[(size_t)(k0 + brow + rr * 8) * HD + n0 + bseg * 8]);
        cp_commit();
    };

    load_stage(0, 0);
    load_stage(1, 64);
    #pragma unroll 1
    for (int it = 0; it < 8; it++) {
        int st = it % 3;
        if (it < 7) cp_wait<1>(); else cp_wait<0>();
        __syncthreads();
        if (it + 2 < 8) load_stage((it + 2) % 3, (it + 2) * 64);
        #pragma unroll
        for (int ks = 0; ks < 64; ks += 16) {
            uint32_t af[4][4], bf[4][4];
            #pragma unroll
            for (int mi = 0; mi < 4; mi++)
                ldsm4(af[mi], smem_u32(&As[st * ASTG +
                    (wm + mi * 16 + (quad & 1) * 8 + r8) * APITCH + ks + (quad >> 1) * 8]));
            #pragma unroll
            for (int nj = 0; nj < 4; nj++)
                ldsm4t(bf[nj], smem_u32(&Bs[st * BSTG +
                    (ks + (quad & 1) * 8 + r8) * BPITCH + wn + nj * 16 + (quad >> 1) * 8]));
            #pragma unroll
            for (int mi = 0; mi < 4; mi++)
                #pragma unroll
                for (int nj = 0; nj < 4; nj++) {
                    mma16816f(acc[mi][2 * nj],     af[mi], &bf[nj][0]);
                    mma16816f(acc[mi][2 * nj + 1], af[mi], &bf[nj][2]);
                }
        }
    }

    int group = lane >> 2, t4 = lane & 3;
    float ss0[4] = {0.f, 0.f, 0.f, 0.f}, ss1[4] = {0.f, 0.f, 0.f, 0.f};
    #pragma unroll
    for (int mi = 0; mi < 4; mi++)
        #pragma unroll
        for (int ni = 0; ni < 8; ni++) {
            int c = n0 + wn + ni * 8 + t4 * 2;
            float b0 = __ldg(&bias[c]), b1 = __ldg(&bias[c + 1]);
            acc[mi][ni][0] += b0; acc[mi][ni][1] += b1;
            acc[mi][ni][2] += b0; acc[mi][ni][3] += b1;
            ss0[mi] += acc[mi][ni][0] * acc[mi][ni][0] + acc[mi][ni][1] * acc[mi][ni][1];
            ss1[mi] += acc[mi][ni][2] * acc[mi][ni][2] + acc[mi][ni][3] * acc[mi][ni][3];
        }

    #pragma unroll
    for (int mi = 0; mi < 4; mi++) {
        ss0[mi] += __shfl_xor_sync(0xffffffffu, ss0[mi], 1);
        ss0[mi] += __shfl_xor_sync(0xffffffffu, ss0[mi], 2);
        ss1[mi] += __shfl_xor_sync(0xffffffffu, ss1[mi], 1);
        ss1[mi] += __shfl_xor_sync(0xffffffffu, ss1[mi], 2);
    }
    float* ssbuf = (float*)smc;
    int wng = warp >> 1;
    if (t4 == 0) {
        #pragma unroll
        for (int mi = 0; mi < 4; mi++) {
            ssbuf[wng * 128 + wm + mi * 16 + group]     = ss0[mi];
            ssbuf[wng * 128 + wm + mi * 16 + group + 8] = ss1[mi];
        }
    }
    __syncthreads();
    #pragma unroll
    for (int mi = 0; mi < 4; mi++) {
        int ra = wm + mi * 16 + group;
        float s0 = ssbuf[ra] + ssbuf[128 + ra] + ssbuf[256 + ra] + ssbuf[384 + ra];
        int rb = ra + 8;
        float s1 = ssbuf[rb] + ssbuf[128 + rb] + ssbuf[256 + rb] + ssbuf[384 + rb];
        float i0 = rsqrtf(s0), i1 = rsqrtf(s1);
        #pragma unroll
        for (int ni = 0; ni < 8; ni++) {
            acc[mi][ni][0] *= i0; acc[mi][ni][1] *= i0;
            acc[mi][ni][2] *= i1; acc[mi][ni][3] *= i1;
        }
    }

    #pragma unroll
    for (int mi = 0; mi < 4; mi++) {
        size_t rA = r0 + wm + mi * 16 + group;
        #pragma unroll
        for (int ni = 0; ni < 8; ni++) {
            int c = n0 + wn + ni * 8 + t4 * 2;
            *(__half2*)&C[rA * HD + c] =
                __floats2half2_rn(acc[mi][ni][0], acc[mi][ni][1]);
            *(__half2*)&C[(rA + 8) * HD + c] =
                __floats2half2_rn(acc[mi][ni][2], acc[mi][ni][3]);
        }
    }

    if (which == 1) {
        float cs[8][2];
        #pragma unroll
        for (int ni = 0; ni < 8; ni++) {
            cs[ni][0] = 0.f; cs[ni][1] = 0.f;
            #pragma unroll
            for (int mi = 0; mi < 4; mi++) {
                cs[ni][0] += acc[mi][ni][0] + acc[mi][ni][2];
                cs[ni][1] += acc[mi][ni][1] + acc[mi][ni][3];
            }
            #pragma unroll
            for (int o = 4; o < 32; o <<= 1) {
                cs[ni][0] += __shfl_xor_sync(0xffffffffu, cs[ni][0], o);
                cs[ni][1] += __shfl_xor_sync(0xffffffffu, cs[ni][1], o);
            }
        }
        __syncthreads();
        float* cbuf = (float*)smc;
        if (lane < 4) {
            #pragma unroll
            for (int ni = 0; ni < 8; ni++) {
                cbuf[warp * 64 + ni * 8 + lane * 2]     = cs[ni][0];
                cbuf[warp * 64 + ni * 8 + lane * 2 + 1] = cs[ni][1];
            }
        }
        __syncthreads();
        int g2 = tid >> 6, cc = tid & 63;
        float s = cbuf[(2 * g2) * 64 + cc] + cbuf[(2 * g2 + 1) * 64 + cc];
        g_ksum_p2[blockIdx.y * HD + n0 + g2 * 64 + cc] = s;
    }
}

// ---------------- ksum final reduce ------------------------------------------
__global__ void ksum_red_kernel() {
    int c = blockIdx.x * 256 + threadIdx.x;   // grid.x = 4
    float s = 0.f;
    for (int p = 0; p < 512; p++) s += g_ksum_p2[p * HD + c];
    g_ksum[c] = s;
}

// ---------------- invden[n,h] = 1/(qn . ksum[h] + N) -------------------------
__global__ void invden_kernel() {
    int wg = blockIdx.x * 8 + (threadIdx.x >> 5);
    int lane = threadIdx.x & 31, h = wg & 3;
    size_t base = (size_t)wg * 256 + lane * 8;
    uint4 raw = *(const uint4*)&g_q[base];
    __half2* p = (__half2*)&raw;
    const float* ks = &g_ksum[h * 256 + lane * 8];
    float s = 0.f;
    #pragma unroll
    for (int i = 0; i < 4; i++) {
        float2 f = __half22float2(p[i]);
        s += f.x * ks[2 * i] + f.y * ks[2 * i + 1];
    }
    #pragma unroll
    for (int o = 16; o > 0; o >>= 1) s += __shfl_xor_sync(0xffffffffu, s, o);
    if (lane == 0) g_invden[wg] = 1.f / (s + 65536.f);
}

// ---------------- C = kn^T @ x : [1024, 512], 9-way split-K ------------------
#define CA_PITCH 136
#define CB_PITCH 264
#define CA_STG (64 * CA_PITCH)
#define CB_STG (64 * CB_PITCH)
#define C_SMEM_BYTES ((3 * (CA_STG + CB_STG)) * 2)
#define NCHUNK 9
#define STRIPS_PER_CHUNK 114

__global__ __launch_bounds__(256) void c_kernel() {
    extern __shared__ __half sm[];
    __half* As = sm;
    __half* Bs = sm + 3 * CA_STG;

    int tid = threadIdx.x, lane = tid & 31, warp = tid >> 5;
    int wm = (warp & 1) * 64, wn = (warp >> 1) * 64;
    int m0 = blockIdx.x * 128;
    int j0 = blockIdx.y * 256;
    int chunk = blockIdx.z;
    int s0 = chunk * STRIPS_PER_CHUNK;
    int s1 = min(1024, s0 + STRIPS_PER_CHUNK);
    int L = s1 - s0;
    int quad = lane >> 3, r8 = lane & 7;
    int arow = tid >> 4, aseg = tid & 15;
    int brow = tid >> 5, bseg = tid & 31;

    float acc[4][8][4];
    #pragma unroll
    for (int a = 0; a < 4; a++)
        #pragma unroll
        for (int b = 0; b < 8; b++)
            #pragma unroll
            for (int c = 0; c < 4; c++) acc[a][b][c] = 0.f;

    auto load_stage = [&](int st, int strip) {
        size_t nb = (size_t)(s0 + strip) * 64;
        #pragma unroll
        for (int rr = 0; rr < 4; rr++)
            cp16(&As[st * CA_STG + (arow + rr * 16) * CA_PITCH + aseg * 8],
                 &g_k[(nb + arow + rr * 16) * HD + m0 + aseg * 8]);
        #pragma unroll
        for (int rr = 0; rr < 8; rr++)
            cp16(&Bs[st * CB_STG + (brow + rr * 8) * CB_PITCH + bseg * 8],
                 &g_xh[(nb + brow + rr * 8) * INC + j0 + bseg * 8]);
        cp_commit();
    };

    load_stage(0, 0);
    load_stage(1, 1);
    #pragma unroll 1
    for (int it = 0; it < L; it++) {
        int st = it % 3;
        if (it < L - 1) cp_wait<1>(); else cp_wait<0>();
        __syncthreads();
        if (it + 2 < L) load_stage((it + 2) % 3, it + 2);
        #pragma unroll
        for (int ks = 0; ks < 64; ks += 16) {
            uint32_t af[4][4], bf[4][4];
            #pragma unroll
            for (int mi = 0; mi < 4; mi++)
                ldsm4t(af[mi], smem_u32(&As[st * CA_STG +
                    (ks + (quad >> 1) * 8 + r8) * CA_PITCH + wm + mi * 16 + (quad & 1) * 8]));
            #pragma unroll
            for (int nj = 0; nj < 4; nj++)
                ldsm4t(bf[nj], smem_u32(&Bs[st * CB_STG +
                    (ks + (quad & 1) * 8 + r8) * CB_PITCH + wn + nj * 16 + (quad >> 1) * 8]));
            #pragma unroll
            for (int mi = 0; mi < 4; mi++)
                #pragma unroll
                for (int nj = 0; nj < 4; nj++) {
                    mma16816f(acc[mi][2 * nj],     af[mi], &bf[nj][0]);
                    mma16816f(acc[mi][2 * nj + 1], af[mi], &bf[nj][2]);
                }
        }
    }
    int group = lane >> 2, t4 = lane & 3;
    float* dst = &g_C_part[(size_t)chunk * (HD * INC)];
    #pragma unroll
    for (int mi = 0; mi < 4; mi++) {
        int rm = m0 + wm + mi * 16 + group;
        #pragma unroll
        for (int ni = 0; ni < 8; ni++) {
            int c = j0 + wn + ni * 8 + t4 * 2;
            *(float2*)&dst[rm * INC + c]       = make_float2(acc[mi][ni][0], acc[mi][ni][1]);
            *(float2*)&dst[(rm + 8) * INC + c] = make_float2(acc[mi][ni][2], acc[mi][ni][3]);
        }
    }
}

__global__ void cred_kernel() {
    int i = blockIdx.x * 256 + threadIdx.x;      // grid = 2048
    float s = 0.f;
    #pragma unroll
    for (int p = 0; p < NCHUNK; p++) s += g_C_part[(size_t)p * (HD * INC) + i];
    g_C[i] = __float2half(s);
}

// -------- kv_h = C_h @ Wv_h + ksum_h (x) bv_h : [4][256][256] -> f16 ---------
__global__ __launch_bounds__(256) void kvsmall_kernel(const float* __restrict__ bv) {
    __shared__ __half As[128][72];
    __shared__ __half Bs[64][136];
    int h = blockIdx.z;
    int m0 = blockIdx.x * 128;
    int d0 = blockIdx.y * 128;
    int tid = threadIdx.x, lane = tid & 31, warp = tid >> 5;
    int wm = (warp & 1) * 64, wn = (warp >> 1) * 32;
    int quad = lane >> 3, r8 = lane & 7;
    int arow = tid >> 3, aseg = tid & 7;
    int brow = tid >> 4, bseg = tid & 15;

    float acc[4][4][4];
    #pragma unroll
    for (int a = 0; a < 4; a++)
        #pragma unroll
        for (int b = 0; b < 4; b++)
            #pragma unroll
            for (int c = 0; c < 4; c++) acc[a][b][c] = 0.f;

    #pragma unroll 1
    for (int kt = 0; kt < 8; kt++) {
        int k0 = kt * 64;
        __syncthreads();
        #pragma unroll
        for (int rr = 0; rr < 4; rr++)
            *(uint4*)&As[arow + rr * 32][aseg * 8] =
                *(const uint4*)&g_C[(size_t)(h * 256 + m0 + arow + rr * 32) * INC + k0 + aseg * 8];
        #pragma unroll
        for (int rr = 0; rr < 4; rr++)
            *(uint4*)&Bs[brow + rr * 16][bseg * 8] =
                *(const uint4*)&g_wh[2][(size_t)(k0 + brow + rr * 16) * HD + h * 256 + d0 + bseg * 8];
        __syncthreads();
        #pragma unroll
        for (int ks = 0; ks < 64; ks += 16) {
            uint32_t af[4][4], bf[2][4];
            #pragma unroll
            for (int mi = 0; mi < 4; mi++)
                ldsm4(af[mi], smem_u32(&As[wm + mi * 16 + (quad & 1) * 8 + r8][ks + (quad >> 1) * 8]));
            #pragma unroll
            for (int nj = 0; nj < 2; nj++)
                ldsm4t(bf[nj], smem_u32(&Bs[ks + (quad & 1) * 8 + r8][wn + nj * 16 + (quad >> 1) * 8]));
            #pragma unroll
            for (int mi = 0; mi < 4; mi++)
                #pragma unroll
                for (int nj = 0; nj < 2; nj++) {
                    mma16816f(acc[mi][2 * nj],     af[mi], &bf[nj][0]);
                    mma16816f(acc[mi][2 * nj + 1], af[mi], &bf[nj][2]);
                }
        }
    }

    int group = lane >> 2, t4 = lane & 3;
    #pragma unroll
    for (int mi = 0; mi < 4; mi++) {
        int rm = m0 + wm + mi * 16 + group;
        float ksA = g_ksum[h * 256 + rm], ksB = g_ksum[h * 256 + rm + 8];
        #pragma unroll
        for (int ni = 0; ni < 4; ni++) {
            int c = d0 + wn + ni * 8 + t4 * 2;
            float b0 = __ldg(&bv[h * 256 + c]), b1 = __ldg(&bv[h * 256 + c + 1]);
            *(__half2*)&g_kvb[(size_t)(h * 256 + rm) * 256 + c] =
                __floats2half2_rn(acc[mi][ni][0] + ksA * b0, acc[mi][ni][1] + ksA * b1);
            *(__half2*)&g_kvb[(size_t)(h * 256 + rm + 8) * 256 + c] =
                __floats2half2_rn(acc[mi][ni][2] + ksB * b0, acc[mi][ni][3] + ksB * b1);
        }
    }
}

// ------ out: 128-row CTAs (512 thr), grid 512, K=1024 ------------------------
#define OAPITCH 72
#define OASTG (128 * OAPITCH)
#define OBSTG (64 * BPITCH)
#define OUT_SMEM_BYTES ((3 * (OASTG + OBSTG)) * 2)

__global__ __launch_bounds__(512) void out_kernel(float* __restrict__ out) {
    extern __shared__ __half sm[];
    __half* As = sm;
    __half* Bs = sm + 3 * OASTG;

    size_t r0 = (size_t)blockIdx.y * 128;
    int tid = threadIdx.x, lane = tid & 31, warp = tid >> 5;
    int wm = (warp & 3) * 32, wn = (warp >> 2) * 64;
    int quad = lane >> 3, r8 = lane & 7;
    int arow = tid >> 3, aseg = tid & 7;
    int brow = tid >> 5, bseg = tid & 31;

    float acc[2][8][4];
    #pragma unroll
    for (int a = 0; a < 2; a++)
        #pragma unroll
        for (int b = 0; b < 8; b++)
            #pragma unroll
            for (int c = 0; c < 4; c++) acc[a][b][c] = 0.f;

    uint4 aR[2];
    float invR[2];

    auto ldgA = [&](int kit) {
        int k0 = kit * 64, h = k0 >> 8;
        #pragma unroll
        for (int rr = 0; rr < 2; rr++) {
            size_t row = r0 + arow + rr * 64;
            aR[rr] = *(const uint4*)&g_q[row * HD + k0 + aseg * 8];
            invR[rr] = g_invden[row * 4 + h];
        }
    };
    auto stsA = [&](int kit) {
        int st = kit % 3;
        #pragma unroll
        for (int rr = 0; rr < 2; rr++) {
            __half2* p = (__half2*)&aR[rr];
            float iv = invR[rr] * 65536.f;
            uint4 o;
            __half2* q = (__half2*)&o;
            #pragma unroll
            for (int j = 0; j < 4; j++) {
                float2 f = __half22float2(p[j]);
                q[j] = __floats2half2_rn(f.x * iv, f.y * iv);
            }
            *(uint4*)&As[st * OASTG + (arow + rr * 64) * OAPITCH + aseg * 8] = o;
        }
    };
    auto cpB = [&](int kit) {
        int st = kit % 3, k0 = kit * 64;
        #pragma unroll
        for (int rr = 0; rr < 4; rr++)
            cp16(&Bs[st * OBSTG + (brow + rr * 16) * BPITCH + bseg * 8],
                 &g_kvb[(size_t)(k0 + brow + rr * 16) * 256 + bseg * 8]);
        cp_commit();
    };

    ldgA(0); stsA(0);
    ldgA(1);
    cpB(0); cpB(1);
    #pragma unroll 1
    for (int it = 0; it < 16; it++) {
        int st = it % 3;
        if (it < 15) cp_wait<1>(); else cp_wait<0>();
        __syncthreads();
        if (it + 1 < 16) stsA(it + 1);
        if (it + 2 < 16) { ldgA(it + 2); cpB(it + 2); }
        #pragma unroll
        for (int ks = 0; ks < 64; ks += 16) {
            uint32_t af[2][4], bf[4][4];
            #pragma unroll
            for (int mi = 0; mi < 2; mi++)
                ldsm4(af[mi], smem_u32(&As[st * OASTG +
                    (wm + mi * 16 + (quad & 1) * 8 + r8) * OAPITCH + ks + (quad >> 1) * 8]));
            #pragma unroll
            for (int nj = 0; nj < 4; nj++)
                ldsm4t(bf[nj], smem_u32(&Bs[st * OBSTG +
                    (ks + (quad & 1) * 8 + r8) * BPITCH + wn + nj * 16 + (quad >> 1) * 8]));
            #pragma unroll
            for (int mi = 0; mi < 2; mi++)
                #pragma unroll
                for (int nj = 0; nj < 4; nj++) {
                    mma16816f(acc[mi][2 * nj],     af[mi], &bf[nj][0]);
                    mma16816f(acc[mi][2 * nj + 1], af[mi], &bf[nj][2]);
                }
        }
    }

    const float inv64k = 1.f / 65536.f;
    int group = lane >> 2, t4 = lane & 3;
    #pragma unroll
    for (int mi = 0; mi < 2; mi++) {
        size_t rA = r0 + wm + mi * 16 + group;
        size_t rB = rA + 8;
        float ia[4], ib[4];
        #pragma unroll
        for (int h = 0; h < 4; h++) {
            ia[h] = g_invden[rA * 4 + h];
            ib[h] = g_invden[rB * 4 + h];
        }
        #pragma unroll
        for (int ni = 0; ni < 8; ni++) {
            int c = wn + ni * 8 + t4 * 2;
            float roa0 = 0.f, roa1 = 0.f, rob0 = 0.f, rob1 = 0.f;
            #pragma unroll
            for (int h = 0; h < 4; h++) {
                float v0 = __ldg(&g_vsum[h * 256 + c]);
                float v1 = __ldg(&g_vsum[h * 256 + c + 1]);
                roa0 += ia[h] * v0; roa1 += ia[h] * v1;
                rob0 += ib[h] * v0; rob1 += ib[h] * v1;
            }
            *(float2*)&out[rA * 256 + c] =
                make_float2(0.25f * (acc[mi][ni][0] * inv64k + roa0),
                            0.25f * (acc[mi][ni][1] * inv64k + roa1));
            *(float2*)&out[rB * 256 + c] =
                make_float2(0.25f * (acc[mi][ni][2] * inv64k + rob0),
                            0.25f * (acc[mi][ni][3] * inv64k + rob1));
        }
    }
}

// ---------------- launch (R12 fork/join topology) ----------------------------
extern "C" void kernel_launch(void* const* d_in, const int* in_sizes, int n_in,
                              void* d_out, int out_size) {
    const float* x  = (const float*)d_in[0];
    const float* Wq = (const float*)d_in[1];
    const float* bq = (const float*)d_in[2];
    const float* Wk = (const float*)d_in[3];
    const float* bk = (const float*)d_in[4];
    const float* Wv = (const float*)d_in[5];
    const float* bv = (const float*)d_in[6];
    float* out = (float*)d_out;

    cudaFuncSetAttribute(qk_kernel,  cudaFuncAttributeMaxDynamicSharedMemorySize, GEMM_SMEM_BYTES);
    cudaFuncSetAttribute(c_kernel,   cudaFuncAttributeMaxDynamicSharedMemorySize, C_SMEM_BYTES);
    cudaFuncSetAttribute(out_kernel, cudaFuncAttributeMaxDynamicSharedMemorySize, OUT_SMEM_BYTES);

    cudaStream_t s1;
    cudaStreamCreateWithFlags(&s1, cudaStreamNonBlocking);
    cudaEvent_t evX, evQK, evSide;
    cudaEventCreateWithFlags(&evX, cudaEventDisableTiming);
    cudaEventCreateWithFlags(&evQK, cudaEventDisableTiming);
    cudaEventCreateWithFlags(&evSide, cudaEventDisableTiming);

    // main stream: the roofline chain
    cvt_x_kernel<<<512, 256>>>(x);
    cudaEventRecord(evX, 0);
    cvt_w_kernel<<<dim3(512, 3), 256>>>(Wq, Wk, Wv);
    qk_kernel<<<dim3(8, 512), 256, GEMM_SMEM_BYTES>>>(bq, bk);
    cudaEventRecord(evQK, 0);

    // side stream: colsum/vsum after cvt_x; ksum/invden after qk
    cudaStreamWaitEvent(s1, evX, 0);
    colsum_red_kernel<<<2, 256, 0, s1>>>();
    vsum_kernel<<<128, 256, 0, s1>>>(Wv, bv);
    cudaStreamWaitEvent(s1, evQK, 0);
    ksum_red_kernel<<<4, 256, 0, s1>>>();
    invden_kernel<<<32768, 256, 0, s1>>>();
    cudaEventRecord(evSide, s1);

    // main: C (overlaps side work), join, kvsmall, out
    c_kernel<<<dim3(8, 2, NCHUNK), 256, C_SMEM_BYTES>>>();
    cred_kernel<<<2048, 256>>>();
    cudaStreamWaitEvent(0, evSide, 0);
    kvsmall_kernel<<<dim3(2, 2, 4), 256>>>(bv);
    out_kernel<<<dim3(1, 512), 512, OUT_SMEM_BYTES>>>(out);
}